// round 2
// baseline (speedup 1.0000x reference)
#include <cuda_runtime.h>
#include <cstdint>
#include <cstddef>

#define EMB    64
#define HDIM   128
#define MUL    64
#define OUTD   448
#define TILE_M 128

#define LDA 68    // emb tile row stride (floats): 68%32=4 -> conflict-free A frags
#define LDH 132   // h buffer row stride: 132%32=4
#define LDB 136   // B operand k-stride: 136%32=8 -> conflict-free B frags

#define SMEM_FLOATS (TILE_M*LDA + TILE_M*LDH + TILE_M*LDB)
#define SMEM_BYTES  (SMEM_FLOATS * 4)

__device__ __forceinline__ float to_tf32(float x) {
    uint32_t u;
    asm("cvt.rna.tf32.f32 %0, %1;" : "=r"(u) : "f"(x));
    return __uint_as_float(u);
}

__device__ __forceinline__ void mma8(float* c, const float* a, const float* b) {
    const uint32_t* A = reinterpret_cast<const uint32_t*>(a);
    const uint32_t* B = reinterpret_cast<const uint32_t*>(b);
    asm volatile(
        "mma.sync.aligned.m16n8k8.row.col.f32.tf32.tf32.f32 "
        "{%0,%1,%2,%3}, {%4,%5,%6,%7}, {%8,%9}, {%0,%1,%2,%3};"
        : "+f"(c[0]), "+f"(c[1]), "+f"(c[2]), "+f"(c[3])
        : "r"(A[0]), "r"(A[1]), "r"(A[2]), "r"(A[3]), "r"(B[0]), "r"(B[1]));
}

__device__ __forceinline__ float silu_f(float x) {
    return x / (1.0f + __expf(-x));
}

// Warp-tiled GEMM: C[128, NFRAG*8*2] += A[128,KDIM] * B[KDIM, ...]
// A in smem row-major (stride LDA_), B in smem [k][n] (stride LDB_).
template<int KDIM, int NFRAG, int LDA_, int LDB_>
__device__ __forceinline__ void gemm_tile(const float* __restrict__ A,
                                          const float* __restrict__ B,
                                          float (&acc)[2][8][4],
                                          int wm, int wn, int lr, int lc) {
    const int nbase = wn * (NFRAG * 8);
#pragma unroll 2
    for (int k0 = 0; k0 < KDIM; k0 += 8) {
        float a[2][4];
#pragma unroll
        for (int mi = 0; mi < 2; mi++) {
            const float* Ar = A + (wm * 32 + mi * 16 + lr) * LDA_ + k0 + lc;
            a[mi][0] = Ar[0];
            a[mi][1] = Ar[8 * LDA_];
            a[mi][2] = Ar[4];
            a[mi][3] = Ar[8 * LDA_ + 4];
        }
        float b[NFRAG][2];
#pragma unroll
        for (int ni = 0; ni < NFRAG; ni++) {
            const float* Bp = B + (k0 + lc) * LDB_ + nbase + ni * 8 + lr;
            b[ni][0] = Bp[0];
            b[ni][1] = Bp[4 * LDB_];
        }
#pragma unroll
        for (int mi = 0; mi < 2; mi++)
#pragma unroll
            for (int ni = 0; ni < NFRAG; ni++)
                mma8(acc[mi][ni], a[mi], b[ni]);
    }
}

__device__ __forceinline__ void zero_acc(float (&acc)[2][8][4]) {
#pragma unroll
    for (int mi = 0; mi < 2; mi++)
#pragma unroll
        for (int ni = 0; ni < 8; ni++)
#pragma unroll
            for (int j = 0; j < 4; j++)
                acc[mi][ni][j] = 0.0f;
}

extern __shared__ float smem[];

__global__ void __launch_bounds__(256, 1)
tpmlp_kernel(const float* __restrict__ emb, const float* __restrict__ x1,
             const float* __restrict__ x2, const float* __restrict__ W0,
             const float* __restrict__ W1, const float* __restrict__ P1,
             const float* __restrict__ P2, const float* __restrict__ P3,
             const float* __restrict__ P4, const float* __restrict__ P5,
             float* __restrict__ out, int Etot) {
    float* sEmb = smem;                        // [128][LDA]
    float* sH   = smem + TILE_M * LDA;         // [128][LDH]
    float* sB   = sH + TILE_M * LDH;           // [128][LDB]

    const int tid  = threadIdx.x;
    const int lane = tid & 31;
    const int wid  = tid >> 5;
    const int wm   = wid >> 1;   // 0..3 (row group of 32)
    const int wn   = wid & 1;    // 0..1 (col group)
    const int lr   = lane >> 2;  // 0..7
    const int lc   = lane & 3;   // 0..3
    const int base = blockIdx.x * TILE_M;

    const float INV_SQRT2  = 0.70710678118654752f;
    const float SQRT3      = 1.7320508075688772f;
    const float SQRT6      = 2.449489742783178f;
    const float INV_SQ_EMB = 0.125f;                 // 1/sqrt(64)
    const float INV_SQ_H   = 0.088388347648318447f;  // 1/sqrt(128)
    const float cA1 = INV_SQRT2 * INV_SQ_H;
    const float cA4 = INV_SQRT2 * INV_SQ_H / SQRT3;
    const float cB  = INV_SQRT2 * INV_SQ_H;
    const float cC  = INV_SQ_H / SQRT6;

    // ---- load emb tile (tf32) + W0 [64][128] ----
    for (int i = tid; i < TILE_M * (EMB / 4); i += 256) {
        int r = i >> 4;
        int c4 = (i & 15) << 2;
        int e = base + r;
        float4 v = make_float4(0.f, 0.f, 0.f, 0.f);
        if (e < Etot) v = *reinterpret_cast<const float4*>(emb + (size_t)e * EMB + c4);
        float* d = sEmb + r * LDA + c4;
        d[0] = to_tf32(v.x); d[1] = to_tf32(v.y); d[2] = to_tf32(v.z); d[3] = to_tf32(v.w);
    }
    for (int i = tid; i < EMB * (HDIM / 4); i += 256) {
        int k = i >> 5;
        int n4 = (i & 31) << 2;
        float4 v = *reinterpret_cast<const float4*>(W0 + k * HDIM + n4);
        float* d = sB + k * LDB + n4;
        d[0] = to_tf32(v.x); d[1] = to_tf32(v.y); d[2] = to_tf32(v.z); d[3] = to_tf32(v.w);
    }
    __syncthreads();

    float acc[2][8][4];

    // ---- GEMM1: h1 = silu(emb @ W0 / sqrt(64)) ----
    zero_acc(acc);
    gemm_tile<EMB, 8, LDA, LDB>(sEmb, sB, acc, wm, wn, lr, lc);
    __syncthreads();  // all reads of sB done

    // store h1 (tf32) ; load W1 into sB
#pragma unroll
    for (int mi = 0; mi < 2; mi++)
#pragma unroll
        for (int ni = 0; ni < 8; ni++)
#pragma unroll
            for (int j = 0; j < 4; j++) {
                int row = wm * 32 + mi * 16 + lr + (j >> 1) * 8;
                int col = wn * 64 + ni * 8 + lc * 2 + (j & 1);
                sH[row * LDH + col] = to_tf32(silu_f(acc[mi][ni][j] * INV_SQ_EMB));
            }
    for (int i = tid; i < HDIM * (HDIM / 4); i += 256) {
        int k = i >> 5;
        int n4 = (i & 31) << 2;
        float4 v = *reinterpret_cast<const float4*>(W1 + k * HDIM + n4);
        float* d = sB + k * LDB + n4;
        d[0] = to_tf32(v.x); d[1] = to_tf32(v.y); d[2] = to_tf32(v.z); d[3] = to_tf32(v.w);
    }
    __syncthreads();

    // ---- GEMM2: h2 = silu(h1 @ W1 / sqrt(128)) ----
    zero_acc(acc);
    gemm_tile<HDIM, 8, LDH, LDB>(sH, sB, acc, wm, wn, lr, lc);
    __syncthreads();  // all reads of sH/sB done before overwrite

    // store h2 (tf32) over sH ; load interleaved {P1,P4} into sB
#pragma unroll
    for (int mi = 0; mi < 2; mi++)
#pragma unroll
        for (int ni = 0; ni < 8; ni++)
#pragma unroll
            for (int j = 0; j < 4; j++) {
                int row = wm * 32 + mi * 16 + lr + (j >> 1) * 8;
                int col = wn * 64 + ni * 8 + lc * 2 + (j & 1);
                sH[row * LDH + col] = to_tf32(silu_f(acc[mi][ni][j] * INV_SQ_H));
            }
    for (int i = tid; i < HDIM * (MUL / 4); i += 256) {
        int k = i >> 4;
        int u4 = (i & 15) << 2;
        float4 va = *reinterpret_cast<const float4*>(P1 + k * MUL + u4);
        float4 vb = *reinterpret_cast<const float4*>(P4 + k * MUL + u4);
        float* d = sB + k * LDB + 2 * u4;
        d[0] = to_tf32(va.x); d[1] = to_tf32(vb.x);
        d[2] = to_tf32(va.y); d[3] = to_tf32(vb.y);
        d[4] = to_tf32(va.z); d[5] = to_tf32(vb.z);
        d[6] = to_tf32(va.w); d[7] = to_tf32(vb.w);
    }
    __syncthreads();

    // ---- Group A: w1 (even cols), w4 (odd cols) -> out[:, 0:64] ----
    zero_acc(acc);
    gemm_tile<HDIM, 8, LDH, LDB>(sH, sB, acc, wm, wn, lr, lc);
    __syncthreads();  // sB reads done

    // load {P2,P3} for group B while epilogue A runs
    for (int i = tid; i < HDIM * (MUL / 4); i += 256) {
        int k = i >> 4;
        int u4 = (i & 15) << 2;
        float4 va = *reinterpret_cast<const float4*>(P2 + k * MUL + u4);
        float4 vb = *reinterpret_cast<const float4*>(P3 + k * MUL + u4);
        float* d = sB + k * LDB + 2 * u4;
        d[0] = to_tf32(va.x); d[1] = to_tf32(vb.x);
        d[2] = to_tf32(va.y); d[3] = to_tf32(vb.y);
        d[4] = to_tf32(va.z); d[5] = to_tf32(vb.z);
        d[6] = to_tf32(va.w); d[7] = to_tf32(vb.w);
    }

#pragma unroll
    for (int mi = 0; mi < 2; mi++)
#pragma unroll
        for (int jr = 0; jr < 2; jr++) {
            int row = wm * 32 + mi * 16 + lr + jr * 8;
            int e = base + row;
            if (e >= Etot) continue;
            float4 xv = __ldg(reinterpret_cast<const float4*>(x2) + e);
            const float* x1r = x1 + (size_t)e * (4 * MUL);
            float* orow = out + (size_t)e * OUTD;
#pragma unroll
            for (int ni = 0; ni < 8; ni++) {
                int u = wn * 32 + ni * 4 + lc;
                float w1 = acc[mi][ni][jr * 2 + 0];
                float w4 = acc[mi][ni][jr * 2 + 1];
                float x10 = __ldg(x1r + u);
                float a0 = __ldg(x1r + 64 + 3 * u);
                float a1 = __ldg(x1r + 64 + 3 * u + 1);
                float a2 = __ldg(x1r + 64 + 3 * u + 2);
                float dot = a0 * xv.y + a1 * xv.z + a2 * xv.w;
                orow[u] = cA1 * w1 * x10 * xv.x + cA4 * w4 * dot;
            }
        }
    __syncthreads();

    // ---- Group B: w2 (even), w3 (odd) -> out[:, 64:256] ----
    zero_acc(acc);
    gemm_tile<HDIM, 8, LDH, LDB>(sH, sB, acc, wm, wn, lr, lc);
    __syncthreads();

    // load P5 for group C
    for (int i = tid; i < HDIM * (MUL / 4); i += 256) {
        int k = i >> 4;
        int u4 = (i & 15) << 2;
        float4 v = *reinterpret_cast<const float4*>(P5 + k * MUL + u4);
        float* d = sB + k * LDB + u4;
        d[0] = to_tf32(v.x); d[1] = to_tf32(v.y); d[2] = to_tf32(v.z); d[3] = to_tf32(v.w);
    }

#pragma unroll
    for (int mi = 0; mi < 2; mi++)
#pragma unroll
        for (int jr = 0; jr < 2; jr++) {
            int row = wm * 32 + mi * 16 + lr + jr * 8;
            int e = base + row;
            if (e >= Etot) continue;
            float4 xv = __ldg(reinterpret_cast<const float4*>(x2) + e);
            const float* x1r = x1 + (size_t)e * (4 * MUL);
            float* orow = out + (size_t)e * OUTD;
#pragma unroll
            for (int ni = 0; ni < 8; ni++) {
                int u = wn * 32 + ni * 4 + lc;
                float w2 = acc[mi][ni][jr * 2 + 0];
                float w3 = acc[mi][ni][jr * 2 + 1];
                float x10 = __ldg(x1r + u);
                float a0 = __ldg(x1r + 64 + 3 * u);
                float a1 = __ldg(x1r + 64 + 3 * u + 1);
                float a2 = __ldg(x1r + 64 + 3 * u + 2);
                float* op = orow + 64 + 3 * u;
                op[0] = cB * (w2 * a0 * xv.x + w3 * x10 * xv.y);
                op[1] = cB * (w2 * a1 * xv.x + w3 * x10 * xv.z);
                op[2] = cB * (w2 * a2 * xv.x + w3 * x10 * xv.w);
            }
        }
    __syncthreads();

    // ---- Group C: w5 -> out[:, 256:448] (N=64, 4 n-frags per warp) ----
    zero_acc(acc);
    gemm_tile<HDIM, 4, LDH, LDB>(sH, sB, acc, wm, wn, lr, lc);

#pragma unroll
    for (int mi = 0; mi < 2; mi++)
#pragma unroll
        for (int jr = 0; jr < 2; jr++) {
            int row = wm * 32 + mi * 16 + lr + jr * 8;
            int e = base + row;
            if (e >= Etot) continue;
            float4 xv = __ldg(reinterpret_cast<const float4*>(x2) + e);
            const float* x1r = x1 + (size_t)e * (4 * MUL);
            float* orow = out + (size_t)e * OUTD;
#pragma unroll
            for (int ni = 0; ni < 4; ni++)
#pragma unroll
                for (int jc = 0; jc < 2; jc++) {
                    int u = wn * 32 + ni * 8 + lc * 2 + jc;
                    float w5 = acc[mi][ni][jr * 2 + jc];
                    float a0 = __ldg(x1r + 64 + 3 * u);
                    float a1 = __ldg(x1r + 64 + 3 * u + 1);
                    float a2 = __ldg(x1r + 64 + 3 * u + 2);
                    float c0 = a1 * xv.w - a2 * xv.z;
                    float c1 = a2 * xv.y - a0 * xv.w;
                    float c2 = a0 * xv.z - a1 * xv.y;
                    float* op = orow + 256 + 3 * u;
                    op[0] = cC * w5 * c0;
                    op[1] = cC * w5 * c1;
                    op[2] = cC * w5 * c2;
                }
        }
}

extern "C" void kernel_launch(void* const* d_in, const int* in_sizes, int n_in,
                              void* d_out, int out_size) {
    const float* emb = (const float*)d_in[0];
    const float* x1  = (const float*)d_in[1];
    const float* x2  = (const float*)d_in[2];
    const float* W0  = (const float*)d_in[3];
    const float* W1  = (const float*)d_in[4];
    const float* P1  = (const float*)d_in[5];
    const float* P2  = (const float*)d_in[6];
    const float* P3  = (const float*)d_in[7];
    const float* P4  = (const float*)d_in[8];
    const float* P5  = (const float*)d_in[9];
    float* out = (float*)d_out;

    int Etot = in_sizes[0] / EMB;
    int grid = (Etot + TILE_M - 1) / TILE_M;

    cudaFuncSetAttribute(tpmlp_kernel, cudaFuncAttributeMaxDynamicSharedMemorySize,
                         SMEM_BYTES);
    tpmlp_kernel<<<grid, 256, SMEM_BYTES>>>(emb, x1, x2, W0, W1, P1, P2, P3, P4, P5,
                                            out, Etot);
}

// round 5
// speedup vs baseline: 1.1356x; 1.1356x over previous
#include <cuda_runtime.h>
#include <cstdint>
#include <cstddef>

#define EMB    64
#define HDIM   128
#define MUL    64
#define OUTD   448
#define TILE_M 128
#define NTHR   512

#define LDA 132   // A/h row stride: 132%32=4 -> conflict-free A frags
#define LDB 136   // B k stride:     136%32=8 -> conflict-free B frags

#define SMEM_FLOATS (TILE_M*LDA + 2*TILE_M*LDB)
#define SMEM_BYTES  (SMEM_FLOATS * 4)

__device__ __forceinline__ float to_tf32(float x) {
    uint32_t u;
    asm("cvt.rna.tf32.f32 %0, %1;" : "=r"(u) : "f"(x));
    return __uint_as_float(u);
}

__device__ __forceinline__ void mma8(float* c, const float* a, const float* b) {
    const uint32_t* A = reinterpret_cast<const uint32_t*>(a);
    const uint32_t* B = reinterpret_cast<const uint32_t*>(b);
    asm volatile(
        "mma.sync.aligned.m16n8k8.row.col.f32.tf32.tf32.f32 "
        "{%0,%1,%2,%3}, {%4,%5,%6,%7}, {%8,%9}, {%0,%1,%2,%3};"
        : "+f"(c[0]), "+f"(c[1]), "+f"(c[2]), "+f"(c[3])
        : "r"(A[0]), "r"(A[1]), "r"(A[2]), "r"(A[3]), "r"(B[0]), "r"(B[1]));
}

__device__ __forceinline__ float silu_f(float x) {
    return x / (1.0f + __expf(-x));
}

// Warp-tiled GEMM: per warp C[32 rows, NFRAG*8 cols] += A[32,KDIM] * B[KDIM,...]
template<int KDIM, int NFRAG>
__device__ __forceinline__ void gemm_tile(const float* __restrict__ A,
                                          const float* __restrict__ B,
                                          float (&acc)[2][4][4],
                                          int wm, int wn, int lr, int lc) {
    const int nbase = wn * (NFRAG * 8);
#pragma unroll 2
    for (int k0 = 0; k0 < KDIM; k0 += 8) {
        float a[2][4];
#pragma unroll
        for (int mi = 0; mi < 2; mi++) {
            const float* Ar = A + (wm * 32 + mi * 16 + lr) * LDA + k0 + lc;
            a[mi][0] = Ar[0];
            a[mi][1] = Ar[8 * LDA];
            a[mi][2] = Ar[4];
            a[mi][3] = Ar[8 * LDA + 4];
        }
        float b[NFRAG][2];
#pragma unroll
        for (int ni = 0; ni < NFRAG; ni++) {
            const float* Bp = B + (k0 + lc) * LDB + nbase + ni * 8 + lr;
            b[ni][0] = Bp[0];
            b[ni][1] = Bp[4 * LDB];
        }
#pragma unroll
        for (int mi = 0; mi < 2; mi++)
#pragma unroll
            for (int ni = 0; ni < NFRAG; ni++)
                mma8(acc[mi][ni], a[mi], b[ni]);
    }
}

__device__ __forceinline__ void zero_acc(float (&acc)[2][4][4]) {
#pragma unroll
    for (int mi = 0; mi < 2; mi++)
#pragma unroll
        for (int ni = 0; ni < 4; ni++)
#pragma unroll
            for (int j = 0; j < 4; j++)
                acc[mi][ni][j] = 0.0f;
}

extern __shared__ float smem[];

__global__ void __launch_bounds__(NTHR, 1)
tpmlp_kernel(const float* __restrict__ emb, const float* __restrict__ x1,
             const float* __restrict__ x2, const float* __restrict__ W0,
             const float* __restrict__ W1, const float* __restrict__ P1,
             const float* __restrict__ P2, const float* __restrict__ P3,
             const float* __restrict__ P4, const float* __restrict__ P5,
             float* __restrict__ out, int Etot) {
    float* sA  = smem;                   // [128][LDA]   emb tile, then h1, then h2
    float* sB0 = smem + TILE_M * LDA;    // [128][LDB]   W0 -> P14 -> P5
    float* sB1 = sB0 + TILE_M * LDB;     // [128][LDB]   W1 -> P23

    const int tid  = threadIdx.x;
    const int lane = tid & 31;
    const int wid  = tid >> 5;
    const int wm   = wid >> 2;   // 0..3 (row group of 32)
    const int wn   = wid & 3;    // 0..3 (col group of 32)
    const int lr   = lane >> 2;  // 0..7
    const int lc   = lane & 3;   // 0..3
    const int base = blockIdx.x * TILE_M;

    const float INV_SQRT2  = 0.70710678118654752f;
    const float SQRT3      = 1.7320508075688772f;
    const float SQRT6      = 2.449489742783178f;
    const float INV_SQ_EMB = 0.125f;
    const float INV_SQ_H   = 0.088388347648318447f;
    const float cA1 = INV_SQRT2 * INV_SQ_H;
    const float cA4 = INV_SQRT2 * INV_SQ_H / SQRT3;
    const float cB  = INV_SQRT2 * INV_SQ_H;
    const float cC  = INV_SQ_H / SQRT6;

    // ---- phase 0: load emb tile, W0 AND W1 (hides W1 latency under GEMM1) ----
    for (int i = tid; i < TILE_M * (EMB / 4); i += NTHR) {
        int r = i >> 4;
        int c4 = (i & 15) << 2;
        int e = base + r;
        float4 v = make_float4(0.f, 0.f, 0.f, 0.f);
        if (e < Etot) v = *reinterpret_cast<const float4*>(emb + (size_t)e * EMB + c4);
        float* d = sA + r * LDA + c4;
        d[0] = to_tf32(v.x); d[1] = to_tf32(v.y); d[2] = to_tf32(v.z); d[3] = to_tf32(v.w);
    }
    for (int i = tid; i < EMB * (HDIM / 4); i += NTHR) {
        int k = i >> 5;
        int n4 = (i & 31) << 2;
        float4 v = *reinterpret_cast<const float4*>(W0 + k * HDIM + n4);
        float* d = sB0 + k * LDB + n4;
        d[0] = to_tf32(v.x); d[1] = to_tf32(v.y); d[2] = to_tf32(v.z); d[3] = to_tf32(v.w);
    }
    for (int i = tid; i < HDIM * (HDIM / 4); i += NTHR) {
        int k = i >> 5;
        int n4 = (i & 31) << 2;
        float4 v = *reinterpret_cast<const float4*>(W1 + k * HDIM + n4);
        float* d = sB1 + k * LDB + n4;
        d[0] = to_tf32(v.x); d[1] = to_tf32(v.y); d[2] = to_tf32(v.z); d[3] = to_tf32(v.w);
    }
    __syncthreads();

    float acc[2][4][4];

    // ---- GEMM1: h1 = silu(emb @ W0 / sqrt(64)) ----
    zero_acc(acc);
    gemm_tile<EMB, 4>(sA, sB0, acc, wm, wn, lr, lc);
    __syncthreads();  // all reads of sA(emb) and sB0(W0) done

    // store h1 (tf32) over sA ; load interleaved {P1,P4} into sB0
#pragma unroll
    for (int mi = 0; mi < 2; mi++)
#pragma unroll
        for (int ni = 0; ni < 4; ni++)
#pragma unroll
            for (int j = 0; j < 4; j++) {
                int row = wm * 32 + mi * 16 + lr + (j >> 1) * 8;
                int col = wn * 32 + ni * 8 + lc * 2 + (j & 1);
                sA[row * LDA + col] = to_tf32(silu_f(acc[mi][ni][j] * INV_SQ_EMB));
            }
    for (int i = tid; i < HDIM * (MUL / 4); i += NTHR) {
        int k = i >> 4;
        int u4 = (i & 15) << 2;
        float4 va = *reinterpret_cast<const float4*>(P1 + k * MUL + u4);
        float4 vb = *reinterpret_cast<const float4*>(P4 + k * MUL + u4);
        float* d = sB0 + k * LDB + 2 * u4;
        d[0] = to_tf32(va.x); d[1] = to_tf32(vb.x);
        d[2] = to_tf32(va.y); d[3] = to_tf32(vb.y);
        d[4] = to_tf32(va.z); d[5] = to_tf32(vb.z);
        d[6] = to_tf32(va.w); d[7] = to_tf32(vb.w);
    }
    __syncthreads();

    // ---- GEMM2: h2 = silu(h1 @ W1 / sqrt(128)) ----
    zero_acc(acc);
    gemm_tile<HDIM, 4>(sA, sB1, acc, wm, wn, lr, lc);
    __syncthreads();  // sA(h1) and sB1(W1) reads done

    // store h2 (tf32) over sA ; load interleaved {P2,P3} into sB1
#pragma unroll
    for (int mi = 0; mi < 2; mi++)
#pragma unroll
        for (int ni = 0; ni < 4; ni++)
#pragma unroll
            for (int j = 0; j < 4; j++) {
                int row = wm * 32 + mi * 16 + lr + (j >> 1) * 8;
                int col = wn * 32 + ni * 8 + lc * 2 + (j & 1);
                sA[row * LDA + col] = to_tf32(silu_f(acc[mi][ni][j] * INV_SQ_H));
            }
    for (int i = tid; i < HDIM * (MUL / 4); i += NTHR) {
        int k = i >> 4;
        int u4 = (i & 15) << 2;
        float4 va = *reinterpret_cast<const float4*>(P2 + k * MUL + u4);
        float4 vb = *reinterpret_cast<const float4*>(P3 + k * MUL + u4);
        float* d = sB1 + k * LDB + 2 * u4;
        d[0] = to_tf32(va.x); d[1] = to_tf32(vb.x);
        d[2] = to_tf32(va.y); d[3] = to_tf32(vb.y);
        d[4] = to_tf32(va.z); d[5] = to_tf32(vb.z);
        d[6] = to_tf32(va.w); d[7] = to_tf32(vb.w);
    }
    __syncthreads();

    // ---- Group A: w1 (even cols), w4 (odd cols) -> out[:, 0:64] ----
    zero_acc(acc);
    gemm_tile<HDIM, 4>(sA, sB0, acc, wm, wn, lr, lc);
    __syncthreads();  // sB0(P14) reads done before overwrite

    // load P5 into sB0 (overlaps with epilogue A)
    for (int i = tid; i < HDIM * (MUL / 4); i += NTHR) {
        int k = i >> 4;
        int u4 = (i & 15) << 2;
        float4 v = *reinterpret_cast<const float4*>(P5 + k * MUL + u4);
        float* d = sB0 + k * LDB + u4;
        d[0] = to_tf32(v.x); d[1] = to_tf32(v.y); d[2] = to_tf32(v.z); d[3] = to_tf32(v.w);
    }

#pragma unroll
    for (int mi = 0; mi < 2; mi++)
#pragma unroll
        for (int jr = 0; jr < 2; jr++) {
            int row = wm * 32 + mi * 16 + lr + jr * 8;
            int e = base + row;
            if (e >= Etot) continue;
            float4 xv = __ldg(reinterpret_cast<const float4*>(x2) + e);
            const float* x1r = x1 + (size_t)e * (4 * MUL);
            float* orow = out + (size_t)e * OUTD;
#pragma unroll
            for (int ni = 0; ni < 4; ni++) {
                int u = wn * 16 + ni * 4 + lc;
                float w1 = acc[mi][ni][jr * 2 + 0];
                float w4 = acc[mi][ni][jr * 2 + 1];
                float x10 = __ldg(x1r + u);
                float a0 = __ldg(x1r + 64 + 3 * u);
                float a1 = __ldg(x1r + 64 + 3 * u + 1);
                float a2 = __ldg(x1r + 64 + 3 * u + 2);
                float dot = a0 * xv.y + a1 * xv.z + a2 * xv.w;
                orow[u] = cA1 * w1 * x10 * xv.x + cA4 * w4 * dot;
            }
        }
    __syncthreads();  // P5 visible in sB0 for GEMM_C

    // ---- Group B: w2 (even), w3 (odd) -> out[:, 64:256] ----
    // Tail (GEMM_B, epi B, GEMM_C, epi C) is barrier-free: per-warp deps only.
    zero_acc(acc);
    gemm_tile<HDIM, 4>(sA, sB1, acc, wm, wn, lr, lc);

#pragma unroll
    for (int mi = 0; mi < 2; mi++)
#pragma unroll
        for (int jr = 0; jr < 2; jr++) {
            int row = wm * 32 + mi * 16 + lr + jr * 8;
            int e = base + row;
            if (e >= Etot) continue;
            float4 xv = __ldg(reinterpret_cast<const float4*>(x2) + e);
            const float* x1r = x1 + (size_t)e * (4 * MUL);
            float* orow = out + (size_t)e * OUTD;
#pragma unroll
            for (int ni = 0; ni < 4; ni++) {
                int u = wn * 16 + ni * 4 + lc;
                float w2 = acc[mi][ni][jr * 2 + 0];
                float w3 = acc[mi][ni][jr * 2 + 1];
                float x10 = __ldg(x1r + u);
                float a0 = __ldg(x1r + 64 + 3 * u);
                float a1 = __ldg(x1r + 64 + 3 * u + 1);
                float a2 = __ldg(x1r + 64 + 3 * u + 2);
                float* op = orow + 64 + 3 * u;
                op[0] = cB * (w2 * a0 * xv.x + w3 * x10 * xv.y);
                op[1] = cB * (w2 * a1 * xv.x + w3 * x10 * xv.z);
                op[2] = cB * (w2 * a2 * xv.x + w3 * x10 * xv.w);
            }
        }

    // ---- Group C: w5 -> out[:, 256:448] (N=64, 2 n-frags per warp) ----
    zero_acc(acc);
    gemm_tile<HDIM, 2>(sA, sB0, acc, wm, wn, lr, lc);

#pragma unroll
    for (int mi = 0; mi < 2; mi++)
#pragma unroll
        for (int jr = 0; jr < 2; jr++) {
            int row = wm * 32 + mi * 16 + lr + jr * 8;
            int e = base + row;
            if (e >= Etot) continue;
            float4 xv = __ldg(reinterpret_cast<const float4*>(x2) + e);
            const float* x1r = x1 + (size_t)e * (4 * MUL);
            float* orow = out + (size_t)e * OUTD;
#pragma unroll
            for (int ni = 0; ni < 2; ni++)
#pragma unroll
                for (int jc = 0; jc < 2; jc++) {
                    int u = wn * 16 + ni * 8 + lc * 2 + jc;
                    float w5 = acc[mi][ni][jr * 2 + jc];
                    float a0 = __ldg(x1r + 64 + 3 * u);
                    float a1 = __ldg(x1r + 64 + 3 * u + 1);
                    float a2 = __ldg(x1r + 64 + 3 * u + 2);
                    float c0 = a1 * xv.w - a2 * xv.z;
                    float c1 = a2 * xv.y - a0 * xv.w;
                    float c2 = a0 * xv.z - a1 * xv.y;
                    float* op = orow + 256 + 3 * u;
                    op[0] = cC * w5 * c0;
                    op[1] = cC * w5 * c1;
                    op[2] = cC * w5 * c2;
                }
        }
}

extern "C" void kernel_launch(void* const* d_in, const int* in_sizes, int n_in,
                              void* d_out, int out_size) {
    const float* emb = (const float*)d_in[0];
    const float* x1  = (const float*)d_in[1];
    const float* x2  = (const float*)d_in[2];
    const float* W0  = (const float*)d_in[3];
    const float* W1  = (const float*)d_in[4];
    const float* P1  = (const float*)d_in[5];
    const float* P2  = (const float*)d_in[6];
    const float* P3  = (const float*)d_in[7];
    const float* P4  = (const float*)d_in[8];
    const float* P5  = (const float*)d_in[9];
    float* out = (float*)d_out;

    int Etot = in_sizes[0] / EMB;
    int grid = (Etot + TILE_M - 1) / TILE_M;

    cudaFuncSetAttribute(tpmlp_kernel, cudaFuncAttributeMaxDynamicSharedMemorySize,
                         SMEM_BYTES);
    tpmlp_kernel<<<grid, NTHR, SMEM_BYTES>>>(emb, x1, x2, W0, W1, P1, P2, P3, P4, P5,
                                             out, Etot);
}

// round 7
// speedup vs baseline: 1.2155x; 1.0703x over previous
#include <cuda_runtime.h>
#include <cstdint>
#include <cstddef>

#define EMB    64
#define HDIM   128
#define MUL    64
#define OUTD   448
#define TILE_M 64
#define NTHR   256

#define LDA 132   // A/h row stride: 132%32=4 -> conflict-free A frags
#define LDB 136   // B k stride:     136%32=8 -> conflict-free B frags

#define SMEM_FLOATS (TILE_M*LDA + TILE_M*LDB*2)   // sA[64][132] + sB[128][136]
#define SMEM_BYTES  (SMEM_FLOATS * 4)

__device__ __forceinline__ float to_tf32(float x) {
    uint32_t u;
    asm("cvt.rna.tf32.f32 %0, %1;" : "=r"(u) : "f"(x));
    return __uint_as_float(u);
}

__device__ __forceinline__ void mma8(float* c, const float* a, const float* b) {
    const uint32_t* A = reinterpret_cast<const uint32_t*>(a);
    const uint32_t* B = reinterpret_cast<const uint32_t*>(b);
    asm volatile(
        "mma.sync.aligned.m16n8k8.row.col.f32.tf32.tf32.f32 "
        "{%0,%1,%2,%3}, {%4,%5,%6,%7}, {%8,%9}, {%0,%1,%2,%3};"
        : "+f"(c[0]), "+f"(c[1]), "+f"(c[2]), "+f"(c[3])
        : "r"(A[0]), "r"(A[1]), "r"(A[2]), "r"(A[3]), "r"(B[0]), "r"(B[1]));
}

__device__ __forceinline__ float silu_f(float x) {
    return x / (1.0f + __expf(-x));
}

// Warp-tiled GEMM: per warp C[32 rows, NFRAG*8 cols] += A[32,KDIM] * B[KDIM,...]
// wm in {0,1} (row group of 32 within 64-row tile), wn in {0..3}.
template<int KDIM, int NFRAG>
__device__ __forceinline__ void gemm_tile(const float* __restrict__ A,
                                          const float* __restrict__ B,
                                          float (&acc)[2][4][4],
                                          int wm, int wn, int lr, int lc) {
    const int nbase = wn * (NFRAG * 8);
#pragma unroll 2
    for (int k0 = 0; k0 < KDIM; k0 += 8) {
        float a[2][4];
#pragma unroll
        for (int mi = 0; mi < 2; mi++) {
            const float* Ar = A + (wm * 32 + mi * 16 + lr) * LDA + k0 + lc;
            a[mi][0] = Ar[0];
            a[mi][1] = Ar[8 * LDA];
            a[mi][2] = Ar[4];
            a[mi][3] = Ar[8 * LDA + 4];
        }
        float b[NFRAG][2];
#pragma unroll
        for (int ni = 0; ni < NFRAG; ni++) {
            const float* Bp = B + (k0 + lc) * LDB + nbase + ni * 8 + lr;
            b[ni][0] = Bp[0];
            b[ni][1] = Bp[4 * LDB];
        }
#pragma unroll
        for (int mi = 0; mi < 2; mi++)
#pragma unroll
            for (int ni = 0; ni < NFRAG; ni++)
                mma8(acc[mi][ni], a[mi], b[ni]);
    }
}

__device__ __forceinline__ void zero_acc(float (&acc)[2][4][4]) {
#pragma unroll
    for (int mi = 0; mi < 2; mi++)
#pragma unroll
        for (int ni = 0; ni < 4; ni++)
#pragma unroll
            for (int j = 0; j < 4; j++)
                acc[mi][ni][j] = 0.0f;
}

extern __shared__ float smem[];

__global__ void __launch_bounds__(NTHR, 2)
tpmlp_kernel(const float* __restrict__ emb, const float* __restrict__ x1,
             const float* __restrict__ x2, const float* __restrict__ W0,
             const float* __restrict__ W1, const float* __restrict__ P1,
             const float* __restrict__ P2, const float* __restrict__ P3,
             const float* __restrict__ P4, const float* __restrict__ P5,
             float* __restrict__ out, int Etot) {
    float* sA = smem;                  // [64][LDA]   emb tile -> h1 -> h2
    float* sB = smem + TILE_M * LDA;   // [128][LDB]  W0 -> W1 -> P14 -> P23 -> P5

    const int tid  = threadIdx.x;
    const int lane = tid & 31;
    const int wid  = tid >> 5;
    const int wm   = wid >> 2;   // 0..1 (row group of 32)
    const int wn   = wid & 3;    // 0..3 (col group of 32)
    const int lr   = lane >> 2;  // 0..7
    const int lc   = lane & 3;   // 0..3
    const int base = blockIdx.x * TILE_M;

    const float INV_SQRT2  = 0.70710678118654752f;
    const float SQRT3      = 1.7320508075688772f;
    const float SQRT6      = 2.449489742783178f;
    const float INV_SQ_EMB = 0.125f;
    const float INV_SQ_H   = 0.088388347648318447f;
    const float cA1 = INV_SQRT2 * INV_SQ_H;
    const float cA4 = INV_SQRT2 * INV_SQ_H / SQRT3;
    const float cB  = INV_SQRT2 * INV_SQ_H;
    const float cC  = INV_SQ_H / SQRT6;

    // ---- phase 0: load emb tile + W0 ----
    for (int i = tid; i < TILE_M * (EMB / 4); i += NTHR) {
        int r = i >> 4;
        int c4 = (i & 15) << 2;
        int e = base + r;
        float4 v = make_float4(0.f, 0.f, 0.f, 0.f);
        if (e < Etot) v = *reinterpret_cast<const float4*>(emb + (size_t)e * EMB + c4);
        float* d = sA + r * LDA + c4;
        d[0] = to_tf32(v.x); d[1] = to_tf32(v.y); d[2] = to_tf32(v.z); d[3] = to_tf32(v.w);
    }
    for (int i = tid; i < EMB * (HDIM / 4); i += NTHR) {
        int k = i >> 5;
        int n4 = (i & 31) << 2;
        float4 v = *reinterpret_cast<const float4*>(W0 + k * HDIM + n4);
        float* d = sB + k * LDB + n4;
        d[0] = to_tf32(v.x); d[1] = to_tf32(v.y); d[2] = to_tf32(v.z); d[3] = to_tf32(v.w);
    }
    __syncthreads();

    float acc[2][4][4];

    // ---- GEMM1: h1 = silu(emb @ W0 / sqrt(64)) ----
    zero_acc(acc);
    gemm_tile<EMB, 4>(sA, sB, acc, wm, wn, lr, lc);
    __syncthreads();  // sA(emb), sB(W0) reads done

    // store h1 (tf32) over sA ; load W1 into sB
#pragma unroll
    for (int mi = 0; mi < 2; mi++)
#pragma unroll
        for (int ni = 0; ni < 4; ni++)
#pragma unroll
            for (int j = 0; j < 4; j++) {
                int row = wm * 32 + mi * 16 + lr + (j >> 1) * 8;
                int col = wn * 32 + ni * 8 + lc * 2 + (j & 1);
                sA[row * LDA + col] = to_tf32(silu_f(acc[mi][ni][j] * INV_SQ_EMB));
            }
    for (int i = tid; i < HDIM * (HDIM / 4); i += NTHR) {
        int k = i >> 5;
        int n4 = (i & 31) << 2;
        float4 v = *reinterpret_cast<const float4*>(W1 + k * HDIM + n4);
        float* d = sB + k * LDB + n4;
        d[0] = to_tf32(v.x); d[1] = to_tf32(v.y); d[2] = to_tf32(v.z); d[3] = to_tf32(v.w);
    }
    __syncthreads();

    // ---- GEMM2: h2 = silu(h1 @ W1 / sqrt(128)) ----
    zero_acc(acc);
    gemm_tile<HDIM, 4>(sA, sB, acc, wm, wn, lr, lc);
    __syncthreads();  // sA(h1), sB(W1) reads done

    // store h2 (tf32) over sA ; load interleaved {P1,P4} into sB
#pragma unroll
    for (int mi = 0; mi < 2; mi++)
#pragma unroll
        for (int ni = 0; ni < 4; ni++)
#pragma unroll
            for (int j = 0; j < 4; j++) {
                int row = wm * 32 + mi * 16 + lr + (j >> 1) * 8;
                int col = wn * 32 + ni * 8 + lc * 2 + (j & 1);
                sA[row * LDA + col] = to_tf32(silu_f(acc[mi][ni][j] * INV_SQ_H));
            }
    for (int i = tid; i < HDIM * (MUL / 4); i += NTHR) {
        int k = i >> 4;
        int u4 = (i & 15) << 2;
        float4 va = *reinterpret_cast<const float4*>(P1 + k * MUL + u4);
        float4 vb = *reinterpret_cast<const float4*>(P4 + k * MUL + u4);
        float* d = sB + k * LDB + 2 * u4;
        d[0] = to_tf32(va.x); d[1] = to_tf32(vb.x);
        d[2] = to_tf32(va.y); d[3] = to_tf32(vb.y);
        d[4] = to_tf32(va.z); d[5] = to_tf32(vb.z);
        d[6] = to_tf32(va.w); d[7] = to_tf32(vb.w);
    }
    __syncthreads();

    // ---- Group A: w1 (even cols), w4 (odd cols) -> out[:, 0:64] ----
    zero_acc(acc);
    gemm_tile<HDIM, 4>(sA, sB, acc, wm, wn, lr, lc);
    __syncthreads();  // sB(P14) reads done before overwrite

    // issue {P2,P3} loads first, then epilogue A (LDG rides under epi compute)
    for (int i = tid; i < HDIM * (MUL / 4); i += NTHR) {
        int k = i >> 4;
        int u4 = (i & 15) << 2;
        float4 va = *reinterpret_cast<const float4*>(P2 + k * MUL + u4);
        float4 vb = *reinterpret_cast<const float4*>(P3 + k * MUL + u4);
        float* d = sB + k * LDB + 2 * u4;
        d[0] = to_tf32(va.x); d[1] = to_tf32(vb.x);
        d[2] = to_tf32(va.y); d[3] = to_tf32(vb.y);
        d[4] = to_tf32(va.z); d[5] = to_tf32(vb.z);
        d[6] = to_tf32(va.w); d[7] = to_tf32(vb.w);
    }

#pragma unroll
    for (int mi = 0; mi < 2; mi++)
#pragma unroll
        for (int jr = 0; jr < 2; jr++) {
            int row = wm * 32 + mi * 16 + lr + jr * 8;
            int e = base + row;
            if (e >= Etot) continue;
            float4 xv = __ldg(reinterpret_cast<const float4*>(x2) + e);
            const float* x1r = x1 + (size_t)e * (4 * MUL);
            float* orow = out + (size_t)e * OUTD;
#pragma unroll
            for (int ni = 0; ni < 4; ni++) {
                int u = wn * 16 + ni * 4 + lc;
                float w1 = acc[mi][ni][jr * 2 + 0];
                float w4 = acc[mi][ni][jr * 2 + 1];
                float x10 = __ldg(x1r + u);
                float a0 = __ldg(x1r + 64 + 3 * u);
                float a1 = __ldg(x1r + 64 + 3 * u + 1);
                float a2 = __ldg(x1r + 64 + 3 * u + 2);
                float dot = a0 * xv.y + a1 * xv.z + a2 * xv.w;
                orow[u] = cA1 * w1 * x10 * xv.x + cA4 * w4 * dot;
            }
        }
    __syncthreads();  // P23 visible

    // ---- Group B: w2 (even), w3 (odd) -> out[:, 64:256] ----
    zero_acc(acc);
    gemm_tile<HDIM, 4>(sA, sB, acc, wm, wn, lr, lc);
    __syncthreads();  // sB(P23) reads done before overwrite

    // issue P5 loads, then epilogue B
    for (int i = tid; i < HDIM * (MUL / 4); i += NTHR) {
        int k = i >> 4;
        int u4 = (i & 15) << 2;
        float4 v = *reinterpret_cast<const float4*>(P5 + k * MUL + u4);
        float* d = sB + k * LDB + u4;
        d[0] = to_tf32(v.x); d[1] = to_tf32(v.y); d[2] = to_tf32(v.z); d[3] = to_tf32(v.w);
    }

#pragma unroll
    for (int mi = 0; mi < 2; mi++)
#pragma unroll
        for (int jr = 0; jr < 2; jr++) {
            int row = wm * 32 + mi * 16 + lr + jr * 8;
            int e = base + row;
            if (e >= Etot) continue;
            float4 xv = __ldg(reinterpret_cast<const float4*>(x2) + e);
            const float* x1r = x1 + (size_t)e * (4 * MUL);
            float* orow = out + (size_t)e * OUTD;
#pragma unroll
            for (int ni = 0; ni < 4; ni++) {
                int u = wn * 16 + ni * 4 + lc;
                float w2 = acc[mi][ni][jr * 2 + 0];
                float w3 = acc[mi][ni][jr * 2 + 1];
                float x10 = __ldg(x1r + u);
                float a0 = __ldg(x1r + 64 + 3 * u);
                float a1 = __ldg(x1r + 64 + 3 * u + 1);
                float a2 = __ldg(x1r + 64 + 3 * u + 2);
                float* op = orow + 64 + 3 * u;
                op[0] = cB * (w2 * a0 * xv.x + w3 * x10 * xv.y);
                op[1] = cB * (w2 * a1 * xv.x + w3 * x10 * xv.z);
                op[2] = cB * (w2 * a2 * xv.x + w3 * x10 * xv.w);
            }
        }
    __syncthreads();  // P5 visible

    // ---- Group C: w5 -> out[:, 256:448] (N=64, 2 n-frags per warp) ----
    zero_acc(acc);
    gemm_tile<HDIM, 2>(sA, sB, acc, wm, wn, lr, lc);

#pragma unroll
    for (int mi = 0; mi < 2; mi++)
#pragma unroll
        for (int jr = 0; jr < 2; jr++) {
            int row = wm * 32 + mi * 16 + lr + jr * 8;
            int e = base + row;
            if (e >= Etot) continue;
            float4 xv = __ldg(reinterpret_cast<const float4*>(x2) + e);
            const float* x1r = x1 + (size_t)e * (4 * MUL);
            float* orow = out + (size_t)e * OUTD;
#pragma unroll
            for (int ni = 0; ni < 2; ni++)
#pragma unroll
                for (int jc = 0; jc < 2; jc++) {
                    int u = wn * 16 + ni * 8 + lc * 2 + jc;
                    float w5 = acc[mi][ni][jr * 2 + jc];
                    float a0 = __ldg(x1r + 64 + 3 * u);
                    float a1 = __ldg(x1r + 64 + 3 * u + 1);
                    float a2 = __ldg(x1r + 64 + 3 * u + 2);
                    float c0 = a1 * xv.w - a2 * xv.z;
                    float c1 = a2 * xv.y - a0 * xv.w;
                    float c2 = a0 * xv.z - a1 * xv.y;
                    float* op = orow + 256 + 3 * u;
                    op[0] = cC * w5 * c0;
                    op[1] = cC * w5 * c1;
                    op[2] = cC * w5 * c2;
                }
        }
}

extern "C" void kernel_launch(void* const* d_in, const int* in_sizes, int n_in,
                              void* d_out, int out_size) {
    const float* emb = (const float*)d_in[0];
    const float* x1  = (const float*)d_in[1];
    const float* x2  = (const float*)d_in[2];
    const float* W0  = (const float*)d_in[3];
    const float* W1  = (const float*)d_in[4];
    const float* P1  = (const float*)d_in[5];
    const float* P2  = (const float*)d_in[6];
    const float* P3  = (const float*)d_in[7];
    const float* P4  = (const float*)d_in[8];
    const float* P5  = (const float*)d_in[9];
    float* out = (float*)d_out;

    int Etot = in_sizes[0] / EMB;
    int grid = (Etot + TILE_M - 1) / TILE_M;

    cudaFuncSetAttribute(tpmlp_kernel, cudaFuncAttributeMaxDynamicSharedMemorySize,
                         SMEM_BYTES);
    tpmlp_kernel<<<grid, NTHR, SMEM_BYTES>>>(emb, x1, x2, W0, W1, P1, P2, P3, P4, P5,
                                             out, Etot);
}

// round 9
// speedup vs baseline: 1.3995x; 1.1514x over previous
#include <cuda_runtime.h>
#include <cstdint>
#include <cstddef>

#define EMB    64
#define HDIM   128
#define MUL    64
#define OUTD   448
#define TILE_M 64
#define NTHR   256

#define LDA 132   // A/h row stride: 132%32=4 -> conflict-free A frags
#define LDB 136   // B k stride:     136%32=8 -> conflict-free B frags
#define LDW 68    // staging stride: 68%32=4 -> conflict-free stage writes

#define SMEM_FLOATS (TILE_M*LDA + HDIM*LDB + 2*16*LDW)
#define SMEM_BYTES  (SMEM_FLOATS * 4)

__device__ __forceinline__ float to_tf32(float x) {
    uint32_t u;
    asm("cvt.rna.tf32.f32 %0, %1;" : "=r"(u) : "f"(x));
    return __uint_as_float(u);
}

__device__ __forceinline__ void mma8(float* c, const float* a, const float* b) {
    const uint32_t* A = reinterpret_cast<const uint32_t*>(a);
    const uint32_t* B = reinterpret_cast<const uint32_t*>(b);
    asm volatile(
        "mma.sync.aligned.m16n8k8.row.col.f32.tf32.tf32.f32 "
        "{%0,%1,%2,%3}, {%4,%5,%6,%7}, {%8,%9}, {%0,%1,%2,%3};"
        : "+f"(c[0]), "+f"(c[1]), "+f"(c[2]), "+f"(c[3])
        : "r"(A[0]), "r"(A[1]), "r"(A[2]), "r"(A[3]), "r"(B[0]), "r"(B[1]));
}

__device__ __forceinline__ float silu_f(float x) {
    return x / (1.0f + __expf(-x));
}

// Warp-tiled GEMM: per warp C[32 rows, NFRAG*8 cols] += A[32,KDIM] * B[KDIM,...]
template<int KDIM, int NFRAG>
__device__ __forceinline__ void gemm_tile(const float* __restrict__ A,
                                          const float* __restrict__ B,
                                          float (&acc)[2][4][4],
                                          int wm, int wn, int lr, int lc) {
    const int nbase = wn * (NFRAG * 8);
#pragma unroll 2
    for (int k0 = 0; k0 < KDIM; k0 += 8) {
        float a[2][4];
#pragma unroll
        for (int mi = 0; mi < 2; mi++) {
            const float* Ar = A + (wm * 32 + mi * 16 + lr) * LDA + k0 + lc;
            a[mi][0] = Ar[0];
            a[mi][1] = Ar[8 * LDA];
            a[mi][2] = Ar[4];
            a[mi][3] = Ar[8 * LDA + 4];
        }
        float b[NFRAG][2];
#pragma unroll
        for (int ni = 0; ni < NFRAG; ni++) {
            const float* Bp = B + (k0 + lc) * LDB + nbase + ni * 8 + lr;
            b[ni][0] = Bp[0];
            b[ni][1] = Bp[4 * LDB];
        }
#pragma unroll
        for (int mi = 0; mi < 2; mi++)
#pragma unroll
            for (int ni = 0; ni < NFRAG; ni++)
                mma8(acc[mi][ni], a[mi], b[ni]);
    }
}

__device__ __forceinline__ void zero_acc(float (&acc)[2][4][4]) {
#pragma unroll
    for (int mi = 0; mi < 2; mi++)
#pragma unroll
        for (int ni = 0; ni < 4; ni++)
#pragma unroll
            for (int j = 0; j < 4; j++)
                acc[mi][ni][j] = 0.0f;
}

extern __shared__ float smem[];

__global__ void __launch_bounds__(NTHR, 2)
tpmlp_kernel(const float* __restrict__ emb, const float* __restrict__ x1,
             const float* __restrict__ x2, const float* __restrict__ W0,
             const float* __restrict__ W1, const float* __restrict__ P1,
             const float* __restrict__ P2, const float* __restrict__ P3,
             const float* __restrict__ P4, const float* __restrict__ P5,
             float* __restrict__ out, int Etot) {
    float* sA  = smem;                    // [64][LDA]  emb -> h1 -> h2
    float* sB  = smem + TILE_M * LDA;     // [128][LDB] W0 -> W1 -> P14 -> P23 -> P5
    float* sWa = sB + HDIM * LDB;         // [16][LDW]  staged w (even member)
    float* sWb = sWa + 16 * LDW;          // [16][LDW]  staged w (odd member)

    const int tid  = threadIdx.x;
    const int lane = tid & 31;
    const int wid  = tid >> 5;
    const int wm   = wid >> 2;   // 0..1 (row group of 32)
    const int wn   = wid & 3;    // 0..3 (col group)
    const int lr   = lane >> 2;  // 0..7
    const int lc   = lane & 3;   // 0..3
    const int base = blockIdx.x * TILE_M;

    // coalesced-epilogue thread mapping: consecutive lanes -> consecutive u
    const int cu = tid & 63;     // 0..63 (u)
    const int cq = tid >> 6;     // 0..3  (row sub-index)

    const float INV_SQRT2  = 0.70710678118654752f;
    const float SQRT3      = 1.7320508075688772f;
    const float SQRT6      = 2.449489742783178f;
    const float INV_SQ_EMB = 0.125f;
    const float INV_SQ_H   = 0.088388347648318447f;
    const float cA1 = INV_SQRT2 * INV_SQ_H;
    const float cA4 = INV_SQRT2 * INV_SQ_H / SQRT3;
    const float cB  = INV_SQRT2 * INV_SQ_H;
    const float cC  = INV_SQ_H / SQRT6;

    // ---- phase 0: load emb tile + W0 ----
    for (int i = tid; i < TILE_M * (EMB / 4); i += NTHR) {
        int r = i >> 4;
        int c4 = (i & 15) << 2;
        int e = base + r;
        float4 v = make_float4(0.f, 0.f, 0.f, 0.f);
        if (e < Etot) v = *reinterpret_cast<const float4*>(emb + (size_t)e * EMB + c4);
        float* d = sA + r * LDA + c4;
        d[0] = to_tf32(v.x); d[1] = to_tf32(v.y); d[2] = to_tf32(v.z); d[3] = to_tf32(v.w);
    }
    for (int i = tid; i < EMB * (HDIM / 4); i += NTHR) {
        int k = i >> 5;
        int n4 = (i & 31) << 2;
        float4 v = *reinterpret_cast<const float4*>(W0 + k * HDIM + n4);
        float* d = sB + k * LDB + n4;
        d[0] = to_tf32(v.x); d[1] = to_tf32(v.y); d[2] = to_tf32(v.z); d[3] = to_tf32(v.w);
    }
    __syncthreads();

    float acc[2][4][4];

    // ---- GEMM1: h1 = silu(emb @ W0 / sqrt(64)) ----
    zero_acc(acc);
    gemm_tile<EMB, 4>(sA, sB, acc, wm, wn, lr, lc);
    __syncthreads();

    // store h1 over sA ; load W1 into sB
#pragma unroll
    for (int mi = 0; mi < 2; mi++)
#pragma unroll
        for (int ni = 0; ni < 4; ni++)
#pragma unroll
            for (int j = 0; j < 4; j++) {
                int row = wm * 32 + mi * 16 + lr + (j >> 1) * 8;
                int col = wn * 32 + ni * 8 + lc * 2 + (j & 1);
                sA[row * LDA + col] = to_tf32(silu_f(acc[mi][ni][j] * INV_SQ_EMB));
            }
    for (int i = tid; i < HDIM * (HDIM / 4); i += NTHR) {
        int k = i >> 5;
        int n4 = (i & 31) << 2;
        float4 v = *reinterpret_cast<const float4*>(W1 + k * HDIM + n4);
        float* d = sB + k * LDB + n4;
        d[0] = to_tf32(v.x); d[1] = to_tf32(v.y); d[2] = to_tf32(v.z); d[3] = to_tf32(v.w);
    }
    __syncthreads();

    // ---- GEMM2: h2 = silu(h1 @ W1 / sqrt(128)) ----
    zero_acc(acc);
    gemm_tile<HDIM, 4>(sA, sB, acc, wm, wn, lr, lc);
    __syncthreads();

    // store h2 over sA ; load interleaved {P1,P4} into sB
#pragma unroll
    for (int mi = 0; mi < 2; mi++)
#pragma unroll
        for (int ni = 0; ni < 4; ni++)
#pragma unroll
            for (int j = 0; j < 4; j++) {
                int row = wm * 32 + mi * 16 + lr + (j >> 1) * 8;
                int col = wn * 32 + ni * 8 + lc * 2 + (j & 1);
                sA[row * LDA + col] = to_tf32(silu_f(acc[mi][ni][j] * INV_SQ_H));
            }
    for (int i = tid; i < HDIM * (MUL / 4); i += NTHR) {
        int k = i >> 4;
        int u4 = (i & 15) << 2;
        float4 va = *reinterpret_cast<const float4*>(P1 + k * MUL + u4);
        float4 vb = *reinterpret_cast<const float4*>(P4 + k * MUL + u4);
        float* d = sB + k * LDB + 2 * u4;
        d[0] = to_tf32(va.x); d[1] = to_tf32(vb.x);
        d[2] = to_tf32(va.y); d[3] = to_tf32(vb.y);
        d[4] = to_tf32(va.z); d[5] = to_tf32(vb.z);
        d[6] = to_tf32(va.w); d[7] = to_tf32(vb.w);
    }
    __syncthreads();

    // ---- Group A GEMM: w1 (even cols), w4 (odd cols) ----
    zero_acc(acc);
    gemm_tile<HDIM, 4>(sA, sB, acc, wm, wn, lr, lc);
    __syncthreads();  // sB(P14) reads done

    // issue {P2,P3} loads (ride under epilogue A)
    for (int i = tid; i < HDIM * (MUL / 4); i += NTHR) {
        int k = i >> 4;
        int u4 = (i & 15) << 2;
        float4 va = *reinterpret_cast<const float4*>(P2 + k * MUL + u4);
        float4 vb = *reinterpret_cast<const float4*>(P3 + k * MUL + u4);
        float* d = sB + k * LDB + 2 * u4;
        d[0] = to_tf32(va.x); d[1] = to_tf32(vb.x);
        d[2] = to_tf32(va.y); d[3] = to_tf32(vb.y);
        d[4] = to_tf32(va.z); d[5] = to_tf32(vb.z);
        d[6] = to_tf32(va.w); d[7] = to_tf32(vb.w);
    }

    // ---- Epilogue A (staged, coalesced): out[:, 0:64] ----
#pragma unroll
    for (int mi = 0; mi < 2; mi++)
#pragma unroll
        for (int jr = 0; jr < 2; jr++) {
#pragma unroll
            for (int ni = 0; ni < 4; ni++) {
                int u = wn * 16 + ni * 4 + lc;
                int q = wm * 8 + lr;
                sWa[q * LDW + u] = acc[mi][ni][jr * 2 + 0];
                sWb[q * LDW + u] = acc[mi][ni][jr * 2 + 1];
            }
            __syncthreads();
#pragma unroll
            for (int p = 0; p < 4; p++) {
                int q = p * 4 + cq;
                int row = (q >> 3) * 32 + mi * 16 + jr * 8 + (q & 7);
                int e = base + row;
                if (e < Etot) {
                    float4 xv = __ldg(reinterpret_cast<const float4*>(x2) + e);
                    const float* x1r = x1 + (size_t)e * (4 * MUL);
                    float w1v = sWa[q * LDW + cu];
                    float w4v = sWb[q * LDW + cu];
                    float x10 = __ldg(x1r + cu);
                    float a0 = __ldg(x1r + 64 + 3 * cu);
                    float a1 = __ldg(x1r + 64 + 3 * cu + 1);
                    float a2 = __ldg(x1r + 64 + 3 * cu + 2);
                    float dot = a0 * xv.y + a1 * xv.z + a2 * xv.w;
                    out[(size_t)e * OUTD + cu] = cA1 * w1v * x10 * xv.x + cA4 * w4v * dot;
                }
            }
            __syncthreads();
        }

    // ---- Group B GEMM: w2 (even), w3 (odd) ----
    zero_acc(acc);
    gemm_tile<HDIM, 4>(sA, sB, acc, wm, wn, lr, lc);
    __syncthreads();  // sB(P23) reads done

    // issue P5 loads (ride under epilogue B)
    for (int i = tid; i < HDIM * (MUL / 4); i += NTHR) {
        int k = i >> 4;
        int u4 = (i & 15) << 2;
        float4 v = *reinterpret_cast<const float4*>(P5 + k * MUL + u4);
        float* d = sB + k * LDB + u4;
        d[0] = to_tf32(v.x); d[1] = to_tf32(v.y); d[2] = to_tf32(v.z); d[3] = to_tf32(v.w);
    }

    // ---- Epilogue B (staged, coalesced): out[:, 64:256] ----
#pragma unroll
    for (int mi = 0; mi < 2; mi++)
#pragma unroll
        for (int jr = 0; jr < 2; jr++) {
#pragma unroll
            for (int ni = 0; ni < 4; ni++) {
                int u = wn * 16 + ni * 4 + lc;
                int q = wm * 8 + lr;
                sWa[q * LDW + u] = acc[mi][ni][jr * 2 + 0];
                sWb[q * LDW + u] = acc[mi][ni][jr * 2 + 1];
            }
            __syncthreads();
#pragma unroll
            for (int p = 0; p < 4; p++) {
                int q = p * 4 + cq;
                int row = (q >> 3) * 32 + mi * 16 + jr * 8 + (q & 7);
                int e = base + row;
                if (e < Etot) {
                    float4 xv = __ldg(reinterpret_cast<const float4*>(x2) + e);
                    const float* x1r = x1 + (size_t)e * (4 * MUL);
                    float w2v = sWa[q * LDW + cu];
                    float w3v = sWb[q * LDW + cu];
                    float x10 = __ldg(x1r + cu);
                    float a0 = __ldg(x1r + 64 + 3 * cu);
                    float a1 = __ldg(x1r + 64 + 3 * cu + 1);
                    float a2 = __ldg(x1r + 64 + 3 * cu + 2);
                    float* op = out + (size_t)e * OUTD + 64 + 3 * cu;
                    op[0] = cB * (w2v * a0 * xv.x + w3v * x10 * xv.y);
                    op[1] = cB * (w2v * a1 * xv.x + w3v * x10 * xv.z);
                    op[2] = cB * (w2v * a2 * xv.x + w3v * x10 * xv.w);
                }
            }
            __syncthreads();
        }

    // ---- Group C GEMM: w5 (N=64, 2 n-frags per warp) ----
    zero_acc(acc);
    gemm_tile<HDIM, 2>(sA, sB, acc, wm, wn, lr, lc);
    __syncthreads();  // ensure sWa free (prior epilogue done)

    // ---- Epilogue C (staged, coalesced): out[:, 256:448] ----
#pragma unroll
    for (int mi = 0; mi < 2; mi++)
#pragma unroll
        for (int jr = 0; jr < 2; jr++) {
#pragma unroll
            for (int ni = 0; ni < 2; ni++)
#pragma unroll
                for (int jc = 0; jc < 2; jc++) {
                    int u = wn * 16 + ni * 8 + lc * 2 + jc;
                    int q = wm * 8 + lr;
                    sWa[q * LDW + u] = acc[mi][ni][jr * 2 + jc];
                }
            __syncthreads();
#pragma unroll
            for (int p = 0; p < 4; p++) {
                int q = p * 4 + cq;
                int row = (q >> 3) * 32 + mi * 16 + jr * 8 + (q & 7);
                int e = base + row;
                if (e < Etot) {
                    float4 xv = __ldg(reinterpret_cast<const float4*>(x2) + e);
                    const float* x1r = x1 + (size_t)e * (4 * MUL);
                    float w5v = sWa[q * LDW + cu];
                    float a0 = __ldg(x1r + 64 + 3 * cu);
                    float a1 = __ldg(x1r + 64 + 3 * cu + 1);
                    float a2 = __ldg(x1r + 64 + 3 * cu + 2);
                    float c0 = a1 * xv.w - a2 * xv.z;
                    float c1 = a2 * xv.y - a0 * xv.w;
                    float c2 = a0 * xv.z - a1 * xv.y;
                    float* op = out + (size_t)e * OUTD + 256 + 3 * cu;
                    op[0] = cC * w5v * c0;
                    op[1] = cC * w5v * c1;
                    op[2] = cC * w5v * c2;
                }
            }
            __syncthreads();
        }
}

extern "C" void kernel_launch(void* const* d_in, const int* in_sizes, int n_in,
                              void* d_out, int out_size) {
    const float* emb = (const float*)d_in[0];
    const float* x1  = (const float*)d_in[1];
    const float* x2  = (const float*)d_in[2];
    const float* W0  = (const float*)d_in[3];
    const float* W1  = (const float*)d_in[4];
    const float* P1  = (const float*)d_in[5];
    const float* P2  = (const float*)d_in[6];
    const float* P3  = (const float*)d_in[7];
    const float* P4  = (const float*)d_in[8];
    const float* P5  = (const float*)d_in[9];
    float* out = (float*)d_out;

    int Etot = in_sizes[0] / EMB;
    int grid = (Etot + TILE_M - 1) / TILE_M;

    cudaFuncSetAttribute(tpmlp_kernel, cudaFuncAttributeMaxDynamicSharedMemorySize,
                         SMEM_BYTES);
    tpmlp_kernel<<<grid, NTHR, SMEM_BYTES>>>(emb, x1, x2, W0, W1, P1, P2, P3, P4, P5,
                                             out, Etot);
}